// round 1
// baseline (speedup 1.0000x reference)
#include <cuda_runtime.h>
#include <cuda_bf16.h>
#include <cstdint>

// Problem constants (fixed by setup_inputs): B=16 graphs, N=4096 nodes/graph,
// 64 features, k=10.
#define KNN_K      10
#define BGRAPHS    16
#define FEATS      64
#define MAX_TOTAL  65536
#define TPB_KNN    256

// Scratch (device globals: no allocation allowed in kernel_launch)
__device__ float g_sum[MAX_TOTAL * FEATS];   // 16 MB accumulators
__device__ int   g_cnt[MAX_TOTAL];           // reverse-degree counts
__device__ int   g_nbr[MAX_TOTAL * KNN_K];   // knn neighbor lists (global idx)

// ---------------------------------------------------------------------------
// K0: zero accumulators + counts (must be inside the graph: replayed each run)
// ---------------------------------------------------------------------------
__global__ void zero_kernel(int n_f4, int n_cnt4) {
    int i = blockIdx.x * blockDim.x + threadIdx.x;
    float4 z = make_float4(0.f, 0.f, 0.f, 0.f);
    if (i < n_f4)  reinterpret_cast<float4*>(g_sum)[i] = z;
    if (i < n_cnt4) reinterpret_cast<int4*>(g_cnt)[i] = make_int4(0, 0, 0, 0);
}

// ---------------------------------------------------------------------------
// K1: brute-force kNN per graph.
//  - each block handles 256 queries of one graph
//  - full graph's positions staged in dynamic smem as float4(x, y, z, |p|^2)
//  - d2 computed EXACTLY like the reference: (sq_i + sq_j) - 2*dot  (cancellation
//    behavior matches jax, minimizing boundary-tie flips)
//  - strict-< insertion keeps the earlier index on ties (top_k stability)
// ---------------------------------------------------------------------------
__global__ void knn_kernel(const float* __restrict__ pos, int N) {
    extern __shared__ float4 sp[];   // N * 16 bytes

    const int tilesPerGraph = N / TPB_KNN;
    const int b    = blockIdx.x / tilesPerGraph;
    const int tile = blockIdx.x % tilesPerGraph;
    const int tid  = threadIdx.x;

    // stage positions for this graph
    const float* pg = pos + (size_t)b * N * 3;
    for (int j = tid; j < N; j += TPB_KNN) {
        float px = pg[j * 3 + 0];
        float py = pg[j * 3 + 1];
        float pz = pg[j * 3 + 2];
        float sq = px * px + py * py + pz * pz;   // matches jnp.sum(pos*pos)
        sp[j] = make_float4(px, py, pz, sq);
    }
    __syncthreads();

    const int ql = tile * TPB_KNN + tid;          // local query index
    const float4 q = sp[ql];
    const float qsq = q.w;

    float kd[KNN_K];
    int   ki[KNN_K];
#pragma unroll
    for (int s = 0; s < KNN_K; ++s) { kd[s] = __int_as_float(0x7f800000); ki[s] = 0; }

#pragma unroll 4
    for (int j = 0; j < N; ++j) {
        float4 p = sp[j];
        float dot = q.x * p.x + q.y * p.y + q.z * p.z;
        float d2  = (qsq + p.w) - 2.0f * dot;
        if (j == ql) d2 = __int_as_float(0x7f800000);   // exclude self
        if (d2 < kd[KNN_K - 1]) {
            float cd = d2; int ci = j;
#pragma unroll
            for (int s = 0; s < KNN_K; ++s) {
                if (cd < kd[s]) {
                    float td = kd[s]; int ti = ki[s];
                    kd[s] = cd; ki[s] = ci;
                    cd = td; ci = ti;
                }
            }
        }
    }

    const int qg = b * N + ql;
#pragma unroll
    for (int s = 0; s < KNN_K; ++s) {
        int jg = b * N + ki[s];
        g_nbr[qg * KNN_K + s] = jg;
        atomicAdd(&g_cnt[jg], 1);
    }
}

// ---------------------------------------------------------------------------
// K2: scatter x[query] into g_sum[neighbor] with vectorized L2 reductions.
// 16 lanes per query, each lane owns a float4 of the feature vector.
// ---------------------------------------------------------------------------
__global__ void scatter_kernel(const float* __restrict__ x, int total) {
    int t = blockIdx.x * blockDim.x + threadIdx.x;
    int q = t >> 4;
    int c = t & 15;
    if (q >= total) return;

    float4 v = reinterpret_cast<const float4*>(x)[q * (FEATS / 4) + c];
    const int* nb = &g_nbr[q * KNN_K];

#pragma unroll
    for (int n = 0; n < KNN_K; ++n) {
        int j = nb[n];
        float* p = g_sum + (size_t)j * FEATS + c * 4;
        asm volatile("red.global.add.v4.f32 [%0], {%1, %2, %3, %4};"
                     :: "l"(p), "f"(v.x), "f"(v.y), "f"(v.z), "f"(v.w)
                     : "memory");
    }
}

// ---------------------------------------------------------------------------
// K3: out[r] = sum_d | x[r,d] - sum[r,d] / max(cnt[r],1) |   (warp per node)
// ---------------------------------------------------------------------------
__global__ void out_kernel(const float* __restrict__ x, float* __restrict__ out,
                           int total) {
    int node = (blockIdx.x * blockDim.x + threadIdx.x) >> 5;
    int lane = threadIdx.x & 31;
    if (node >= total) return;

    float c   = (float)g_cnt[node];
    float inv = 1.0f / fmaxf(c, 1.0f);

    const float* xr = x + (size_t)node * FEATS;
    const float* sr = g_sum + (size_t)node * FEATS;

    float acc = fabsf(xr[lane]      - sr[lane]      * inv)
              + fabsf(xr[lane + 32] - sr[lane + 32] * inv);
#pragma unroll
    for (int o = 16; o > 0; o >>= 1) acc += __shfl_xor_sync(0xffffffffu, acc, o);
    if (lane == 0) out[node] = acc;
}

// ---------------------------------------------------------------------------
extern "C" void kernel_launch(void* const* d_in, const int* in_sizes, int n_in,
                              void* d_out, int out_size) {
    const float* x   = (const float*)d_in[0];   // [total, 64] fp32
    const float* pos = (const float*)d_in[1];   // [total, 3]  fp32
    // d_in[2] = batch (int64, implied by equal-sized graphs), d_in[3] = k (10)

    const int total = in_sizes[0] / FEATS;      // 65536
    const int N     = total / BGRAPHS;          // 4096
    float* out = (float*)d_out;

    // K0: zero accumulators + counts
    int n_f4   = total * FEATS / 4;
    int n_cnt4 = total / 4;
    zero_kernel<<<(n_f4 + 255) / 256, 256>>>(n_f4, n_cnt4);

    // K1: kNN (dynamic smem = N * 16 bytes = 64 KB)
    size_t smem = (size_t)N * sizeof(float4);
    cudaFuncSetAttribute(knn_kernel, cudaFuncAttributeMaxDynamicSharedMemorySize,
                         (int)smem);
    knn_kernel<<<total / TPB_KNN, TPB_KNN, smem>>>(pos, N);

    // K2: vectorized atomic scatter (16 lanes per query)
    int threads2 = total * 16;
    scatter_kernel<<<(threads2 + 127) / 128, 128>>>(x, total);

    // K3: finalize L1 norm (warp per node)
    out_kernel<<<(total * 32 + 255) / 256, 256>>>(x, out, total);
}

// round 2
// speedup vs baseline: 1.0590x; 1.0590x over previous
#include <cuda_runtime.h>
#include <cuda_bf16.h>
#include <cstdint>

// Problem constants: B=16 graphs, N=4096 nodes/graph, 64 features, k=10.
#define KNN_K      10
#define BGRAPHS    16
#define FEATS      64
#define MAX_TOTAL  65536
#define TPB_KNN    256

// Scratch (device globals: no allocation allowed in kernel_launch)
__device__ float g_sum[MAX_TOTAL * FEATS];   // 16 MB accumulators
__device__ int   g_cnt[MAX_TOTAL];           // reverse-degree counts
__device__ int   g_nbr[MAX_TOTAL * KNN_K];   // knn neighbor lists (global idx)

// ---------- packed f32x2 helpers (sm_103a) ----------
__device__ __forceinline__ uint64_t pack2(float a, float b) {
    uint64_t r; asm("mov.b64 %0, {%1, %2};" : "=l"(r) : "f"(a), "f"(b)); return r;
}
__device__ __forceinline__ void unpack2(float& lo, float& hi, uint64_t v) {
    asm("mov.b64 {%0, %1}, %2;" : "=f"(lo), "=f"(hi) : "l"(v));
}
__device__ __forceinline__ uint64_t mul2(uint64_t a, uint64_t b) {
    uint64_t r; asm("mul.rn.f32x2 %0, %1, %2;" : "=l"(r) : "l"(a), "l"(b)); return r;
}
__device__ __forceinline__ uint64_t add2(uint64_t a, uint64_t b) {
    uint64_t r; asm("add.rn.f32x2 %0, %1, %2;" : "=l"(r) : "l"(a), "l"(b)); return r;
}
__device__ __forceinline__ uint64_t fma2(uint64_t a, uint64_t b, uint64_t c) {
    uint64_t r; asm("fma.rn.f32x2 %0, %1, %2, %3;" : "=l"(r) : "l"(a), "l"(b), "l"(c)); return r;
}

// ---------------------------------------------------------------------------
// K1: brute-force kNN per graph, packed f32x2 fast path, fused zeroing.
// smem layout (pair-transposed so one LDS.128 yields packed f32x2 operands):
//   sxy[jp] = {x(2jp), x(2jp+1), y(2jp), y(2jp+1)}
//   szw[jp] = {z(2jp), z(2jp+1), w(2jp), w(2jp+1)}   w = |p|^2
// d2 per lane = (qsq + w) - 2*dot, identical rounding to the reference-matching
// scalar code. Self-distance is exactly 0 and is filtered in the slow path.
// ---------------------------------------------------------------------------
__global__ void __launch_bounds__(TPB_KNN) knn_kernel(const float* __restrict__ pos, int N) {
    extern __shared__ float4 sm[];
    float4* sxy = sm;             // N/2 entries
    float4* szw = sm + (N >> 1);  // N/2 entries

    const int tilesPerGraph = N / TPB_KNN;
    const int b    = blockIdx.x / tilesPerGraph;
    const int tile = blockIdx.x % tilesPerGraph;
    const int tid  = threadIdx.x;

    // ---- fused zeroing: this block owns queries [qbase, qbase+256) ----
    const int qbase = b * N + tile * TPB_KNN;
    {
        float4 z = make_float4(0.f, 0.f, 0.f, 0.f);
        float4* dst = reinterpret_cast<float4*>(g_sum) + (size_t)qbase * (FEATS / 4);
#pragma unroll
        for (int i = 0; i < 16; ++i) dst[i * TPB_KNN + tid] = z;
        g_cnt[qbase + tid] = 0;
    }

    // ---- stage positions (pair-transposed) ----
    const float* pg = pos + (size_t)b * N * 3;
    for (int jp = tid; jp < (N >> 1); jp += TPB_KNN) {
        int j0 = jp * 2;
        float x0 = pg[3*j0+0], y0 = pg[3*j0+1], z0 = pg[3*j0+2];
        float x1 = pg[3*j0+3], y1 = pg[3*j0+4], z1 = pg[3*j0+5];
        float w0 = x0*x0 + y0*y0 + z0*z0;
        float w1 = x1*x1 + y1*y1 + z1*z1;
        sxy[jp] = make_float4(x0, x1, y0, y1);
        szw[jp] = make_float4(z0, z1, w0, w1);
    }
    __syncthreads();

    // ---- own query ----
    const int ql = tile * TPB_KNN + tid;
    float qx, qy, qz, qsq;
    {
        float4 xy = sxy[ql >> 1];
        float4 zw = szw[ql >> 1];
        if (ql & 1) { qx = xy.y; qy = xy.w; qz = zw.y; qsq = zw.w; }
        else        { qx = xy.x; qy = xy.z; qz = zw.x; qsq = zw.z; }
    }
    const uint64_t qx2  = pack2(qx, qx);
    const uint64_t qy2  = pack2(qy, qy);
    const uint64_t qz2  = pack2(qz, qz);
    const uint64_t qsq2 = pack2(qsq, qsq);
    const uint64_t m2   = pack2(-2.0f, -2.0f);

    float kd[KNN_K];
    int   ki[KNN_K];
#pragma unroll
    for (int s = 0; s < KNN_K; ++s) { kd[s] = __int_as_float(0x7f800000); ki[s] = 0; }
    float thr = kd[KNN_K - 1];

    const ulonglong2* pxy = reinterpret_cast<const ulonglong2*>(sxy);
    const ulonglong2* pzw = reinterpret_cast<const ulonglong2*>(szw);

#pragma unroll 4
    for (int jp = 0; jp < (N >> 1); ++jp) {
        ulonglong2 xy = pxy[jp];   // .x = {x0,x1}, .y = {y0,y1}
        ulonglong2 zw = pzw[jp];   // .x = {z0,z1}, .y = {w0,w1}
        uint64_t dot = mul2(qx2, xy.x);
        dot = fma2(qy2, xy.y, dot);
        dot = fma2(qz2, zw.x, dot);
        uint64_t s2  = add2(qsq2, zw.y);
        uint64_t d2p = fma2(m2, dot, s2);
        float lo, hi; unpack2(lo, hi, d2p);
        if ((lo < thr) | (hi < thr)) {
            int j0 = jp * 2;
            if (lo < thr && j0 != ql) {
                float cd = lo; int ci = j0;
#pragma unroll
                for (int s = 0; s < KNN_K; ++s)
                    if (cd < kd[s]) { float td = kd[s]; int ti = ki[s];
                                      kd[s] = cd; ki[s] = ci; cd = td; ci = ti; }
                thr = kd[KNN_K - 1];
            }
            if (hi < thr && (j0 + 1) != ql) {
                float cd = hi; int ci = j0 + 1;
#pragma unroll
                for (int s = 0; s < KNN_K; ++s)
                    if (cd < kd[s]) { float td = kd[s]; int ti = ki[s];
                                      kd[s] = cd; ki[s] = ci; cd = td; ci = ti; }
                thr = kd[KNN_K - 1];
            }
        }
    }

    const int qg = qbase + tid;
#pragma unroll
    for (int s = 0; s < KNN_K; ++s)
        g_nbr[qg * KNN_K + s] = b * N + ki[s];
}

// ---------------------------------------------------------------------------
// K2: scatter x[query] into g_sum[neighbor] with vectorized L2 reductions,
// plus reverse-degree counting (lane 0 of each 16-lane query group).
// ---------------------------------------------------------------------------
__global__ void scatter_kernel(const float* __restrict__ x, int total) {
    int t = blockIdx.x * blockDim.x + threadIdx.x;
    int q = t >> 4;
    int c = t & 15;
    if (q >= total) return;

    float4 v = reinterpret_cast<const float4*>(x)[q * (FEATS / 4) + c];
    const int* nb = &g_nbr[q * KNN_K];

#pragma unroll
    for (int n = 0; n < KNN_K; ++n) {
        int j = nb[n];
        float* p = g_sum + (size_t)j * FEATS + c * 4;
        asm volatile("red.global.add.v4.f32 [%0], {%1, %2, %3, %4};"
                     :: "l"(p), "f"(v.x), "f"(v.y), "f"(v.z), "f"(v.w)
                     : "memory");
        if (c == 0)
            asm volatile("red.global.add.u32 [%0], %1;"
                         :: "l"(&g_cnt[j]), "r"(1) : "memory");
    }
}

// ---------------------------------------------------------------------------
// K3: out[r] = sum_d | x[r,d] - sum[r,d] / max(cnt[r],1) |   (warp per node)
// ---------------------------------------------------------------------------
__global__ void out_kernel(const float* __restrict__ x, float* __restrict__ out,
                           int total) {
    int node = (blockIdx.x * blockDim.x + threadIdx.x) >> 5;
    int lane = threadIdx.x & 31;
    if (node >= total) return;

    float c   = (float)g_cnt[node];
    float inv = 1.0f / fmaxf(c, 1.0f);

    const float* xr = x + (size_t)node * FEATS;
    const float* sr = g_sum + (size_t)node * FEATS;

    float acc = fabsf(xr[lane]      - sr[lane]      * inv)
              + fabsf(xr[lane + 32] - sr[lane + 32] * inv);
#pragma unroll
    for (int o = 16; o > 0; o >>= 1) acc += __shfl_xor_sync(0xffffffffu, acc, o);
    if (lane == 0) out[node] = acc;
}

// ---------------------------------------------------------------------------
extern "C" void kernel_launch(void* const* d_in, const int* in_sizes, int n_in,
                              void* d_out, int out_size) {
    const float* x   = (const float*)d_in[0];   // [total, 64] fp32
    const float* pos = (const float*)d_in[1];   // [total, 3]  fp32

    const int total = in_sizes[0] / FEATS;      // 65536
    const int N     = total / BGRAPHS;          // 4096
    float* out = (float*)d_out;

    // K1: kNN with fused zeroing (dynamic smem = N * 16 bytes = 64 KB)
    size_t smem = (size_t)N * sizeof(float4);
    cudaFuncSetAttribute(knn_kernel, cudaFuncAttributeMaxDynamicSharedMemorySize,
                         (int)smem);
    knn_kernel<<<total / TPB_KNN, TPB_KNN, smem>>>(pos, N);

    // K2: vectorized atomic scatter + counts (16 lanes per query)
    int threads2 = total * 16;
    scatter_kernel<<<(threads2 + 127) / 128, 128>>>(x, total);

    // K3: finalize L1 norm (warp per node)
    out_kernel<<<(total * 32 + 255) / 256, 256>>>(x, out, total);
}